// round 15
// baseline (speedup 1.0000x reference)
#include <cuda_runtime.h>
#include <cstdint>

// Quantizer — VQ assignment via mma.sync tf32 3-term split (sm_100-safe PTX).
//   x [B,H,L,D] f32, c_sum [H,S,D] f32, c_count [H,S] f32
//   out = [delta_onehot [B,H,L,S] f32 | c [H,S,D] f32]
// score_s = |c_s|^2 + x.(-2 c_s); 3-term tf32 split, fp32 accumulate
// (residual ~1e-5 << argmin gaps; rel_err 0.0 R7-R14).
// R14 -> R15: ping-pong accumulators; chunk p-1's argmin/zero-fill/arrive
// runs AFTER chunk p's MMAs are issued, so the serial tail (scoreboard wait
// + ~150cyc ALU) executes under chunk p's tensor-pipe shadow. +32 regs.

#define Bq 4
#define Hq 16
#define Lq 4096
#define Dq 64
#define Sq 512
#define ONEHOT_ELEMS ((size_t)Bq * Hq * Lq * Sq)

#define ROWS 128
#define NTHR 128
#define CH   32
#define RSTRIDE 136                        // padded row (floats)
#define SLOT_F  (CH * RSTRIDE)             // 4352 floats = 17408 B per chunk
#define CHUNK_BYTES (SLOT_F * 4)
#define NCHUNK  (Sq / CH)                  // 16

// Codebook scratch, PRE-PADDED chunk layout: per (h,chunk): 32 rows x
// [hi 64 | lo 64 | pad 8] floats, rows k-permuted for mma B fragments.
__device__ float g_cbB[Hq * NCHUNK * SLOT_F];   // ~4.5 MB
__device__ float g_c2[Hq * Sq];                 // 32 KB

// -------------------- helpers --------------------
__device__ __forceinline__ uint32_t smem_u32(const void* p) {
    uint32_t a;
    asm("{ .reg .u64 t; cvta.to.shared.u64 t, %1; cvt.u32.u64 %0, t; }"
        : "=r"(a) : "l"(p));
    return a;
}
__device__ __forceinline__ float to_tf32(float x) {
    uint32_t u;
    asm("cvt.rna.tf32.f32 %0, %1;" : "=r"(u) : "f"(x));
    return __uint_as_float(u);
}

#define MBAR_INIT(a, n) \
    asm volatile("mbarrier.init.shared.b64 [%0], %1;" :: "r"(a), "r"(n) : "memory")
#define MBAR_EXPECT_TX(a, tx) \
    asm volatile("mbarrier.arrive.expect_tx.shared.b64 _, [%0], %1;" \
                 :: "r"(a), "r"(tx) : "memory")
#define MBAR_ARRIVE(a) \
    asm volatile("mbarrier.arrive.shared.b64 _, [%0];" :: "r"(a) : "memory")
#define MBAR_WAIT(a, ph) do {                                              \
    uint32_t _m = (a), _p = (ph), _d;                                      \
    asm volatile("{\n\t.reg .pred p;\n\t"                                  \
        "mbarrier.try_wait.parity.acquire.cta.shared::cta.b64 p, [%1], %2;\n\t" \
        "selp.b32 %0, 1, 0, p;\n\t}" : "=r"(_d) : "r"(_m), "r"(_p) : "memory"); \
    if (!_d) {                                                             \
        asm volatile("{\n\t.reg .pred P1;\n\tWL%=:\n\t"                    \
            "mbarrier.try_wait.parity.acquire.cta.shared::cta.b64 P1, [%0], %1, 0x989680;\n\t" \
            "@P1 bra.uni WD%=;\n\tbra.uni WL%=;\n\tWD%=:\n\t}"             \
            :: "r"(_m), "r"(_p) : "memory");                               \
    }                                                                      \
} while (0)

__device__ __forceinline__ void bulk_cp(uint32_t dst, const void* src,
                                        uint32_t bytes, uint32_t mbar) {
    asm volatile(
        "cp.async.bulk.shared::cta.global.mbarrier::complete_tx::bytes "
        "[%0], [%1], %2, [%3];"
        :: "r"(dst), "l"(src), "r"(bytes), "r"(mbar) : "memory");
}

// m16n8k8 tf32 row.col; operand mapping verified R6-R14 (rel_err 0.0).
__device__ __forceinline__ void mma1688(float4& d, float2 a0, float2 a1, float2 b) {
    asm("mma.sync.aligned.m16n8k8.row.col.f32.tf32.tf32.f32 "
        "{%0,%1,%2,%3}, {%4,%5,%6,%7}, {%8,%9}, {%0,%1,%2,%3};"
        : "+f"(d.x), "+f"(d.y), "+f"(d.z), "+f"(d.w)
        : "r"(__float_as_uint(a0.x)), "r"(__float_as_uint(a1.x)),
          "r"(__float_as_uint(a0.y)), "r"(__float_as_uint(a1.y)),
          "r"(__float_as_uint(b.x)),  "r"(__float_as_uint(b.y)));
}

// k-permutation: pos(k) puts (m, m+4) adjacent within each 8-block.
__device__ __forceinline__ int kpos(int k) {
    return (k & ~7) + ((k & 3) << 1) + ((k >> 2) & 1);
}

// -------------------- prep --------------------
__global__ void prep_kernel(const float* __restrict__ c_sum,
                            const float* __restrict__ c_count,
                            float* __restrict__ out_c) {
    const int cw = blockIdx.x;            // h*S + s
    const int lane = threadIdx.x;         // 2 dims per lane
    const int h = cw >> 9, s = cw & 511;
    float cnt = fmaxf(c_count[cw], 1e-6f);

    float2 v = ((const float2*)(c_sum + (size_t)cw * Dq))[lane];
    float a = v.x / cnt;                  // IEEE divide: matches reference
    float b = v.y / cnt;
    ((float2*)(out_c + (size_t)cw * Dq))[lane] = make_float2(a, b);

    float* row = g_cbB + ((size_t)(h * NCHUNK + (s >> 5)) * SLOT_F)
                       + (size_t)(s & 31) * RSTRIDE;
    int k0 = 2 * lane, k1 = 2 * lane + 1;
    float m0 = -2.0f * a, m1 = -2.0f * b;
    float h0 = to_tf32(m0), h1 = to_tf32(m1);
    row[kpos(k0)]      = h0;
    row[kpos(k1)]      = h1;
    row[64 + kpos(k0)] = to_tf32(m0 - h0);
    row[64 + kpos(k1)] = to_tf32(m1 - h1);

    float sq = a * a + b * b;
    #pragma unroll
    for (int o = 16; o > 0; o >>= 1) sq += __shfl_xor_sync(0xFFFFFFFFu, sq, o);
    if (lane == 0) g_c2[cw] = sq;
}

// -------------------- main --------------------
#define AREG_F  (ROWS * RSTRIDE)      // 17408 floats (holds slots 2,3)
#define B0_F    AREG_F                // slot 0: 17408
#define B1_F    (B0_F + SLOT_F)      // slot 1: 21760
#define C2_F    (B1_F + SLOT_F)      // 26112
#define IDX_F   (C2_F + Sq)          // 26624
#define MBAR_F  (IDX_F + ROWS)       // 26752
#define SMEM_TOTAL (MBAR_F * 4 + 64)

__global__ __launch_bounds__(NTHR, 2)
void vq_kernel(const float* __restrict__ x, float* __restrict__ out) {
    extern __shared__ float sm[];
    const uint32_t sb = smem_u32(sm);
    const int tid = threadIdx.x;
    const int wid = tid >> 5, lane = tid & 31;
    const int g = lane >> 2, m = lane & 3;
    const int wb = wid * 32;

    const int rowbase = blockIdx.x * ROWS;
    const int h = (blockIdx.x >> 5) & (Hq - 1);   // 32 CTAs per (b,h)
    const char* cbb = (const char*)(g_cbB + (size_t)h * NCHUNK * SLOT_F);

    const uint32_t slot_f[4] = {B0_F, B1_F, 0u, SLOT_F};
    const uint32_t mb_full  = sb + MBAR_F * 4;         // 4 x 8B
    const uint32_t mb_empty = mb_full + 32;            // 4 x 8B

    if (tid == 0) {
        #pragma unroll
        for (int i = 0; i < 4; ++i) {
            MBAR_INIT(mb_full + 8 * i, 1);
            MBAR_INIT(mb_empty + 8 * i, 4);
        }
    }
    __syncthreads();                       // barrier init visible

    // Producer prologue: chunks 0,1 -> slots 0,1 (disjoint from A region).
    if (tid == 0) {
        MBAR_EXPECT_TX(mb_full + 0, CHUNK_BYTES);
        bulk_cp(sb + B0_F * 4, cbb, CHUNK_BYTES, mb_full + 0);
        MBAR_EXPECT_TX(mb_full + 8, CHUNK_BYTES);
        bulk_cp(sb + B1_F * 4, cbb + CHUNK_BYTES, CHUNK_BYTES, mb_full + 8);
    }

    // Stage c2 + A tile (hi/lo tf32, k-permuted, padded rows).
    for (int i = tid; i < Sq; i += NTHR) sm[C2_F + i] = g_c2[h * Sq + i];
    {
        const float4* xb = (const float4*)(x + (size_t)rowbase * Dq);
        #pragma unroll
        for (int it = 0; it < 8; ++it) {
            int i = it * NTHR + tid;          // 128 rows x 8 kblocks
            int r = i >> 3, kb = i & 7;
            float4 v0 = xb[r * 16 + kb * 2];
            float4 v1 = xb[r * 16 + kb * 2 + 1];
            float h0 = to_tf32(v0.x), h1 = to_tf32(v0.y),
                  h2 = to_tf32(v0.z), h3 = to_tf32(v0.w),
                  h4 = to_tf32(v1.x), h5 = to_tf32(v1.y),
                  h6 = to_tf32(v1.z), h7 = to_tf32(v1.w);
            float l0 = to_tf32(v0.x - h0), l1 = to_tf32(v0.y - h1),
                  l2 = to_tf32(v0.z - h2), l3 = to_tf32(v0.w - h3),
                  l4 = to_tf32(v1.x - h4), l5 = to_tf32(v1.y - h5),
                  l6 = to_tf32(v1.z - h6), l7 = to_tf32(v1.w - h7);
            float* dh = sm + r * RSTRIDE + kb * 8;
            ((float4*)dh)[0] = make_float4(h0, h4, h1, h5);
            ((float4*)dh)[1] = make_float4(h2, h6, h3, h7);
            float* dl = dh + 64;
            ((float4*)dl)[0] = make_float4(l0, l4, l1, l5);
            ((float4*)dl)[1] = make_float4(l2, l6, l3, l7);
        }
    }
    __syncthreads();

    // A fragments to registers: [tile][kblock][row-half], hi and lo.
    float2 Ah[2][8][2], Al[2][8][2];
    #pragma unroll
    for (int t = 0; t < 2; ++t)
        #pragma unroll
        for (int kb = 0; kb < 8; ++kb) {
            int r0 = wb + t * 16 + g;
            const float* b0 = sm + r0 * RSTRIDE + kb * 8 + m * 2;
            const float* b8 = b0 + 8 * RSTRIDE;
            Ah[t][kb][0] = *(const float2*)b0;
            Ah[t][kb][1] = *(const float2*)b8;
            Al[t][kb][0] = *(const float2*)(b0 + 64);
            Al[t][kb][1] = *(const float2*)(b8 + 64);
        }
    __syncthreads();   // A region dead -> slots 2,3 may be filled

    if (tid == 0) {
        MBAR_EXPECT_TX(mb_full + 16, CHUNK_BYTES);
        bulk_cp(sb + 0, cbb + 2 * (size_t)CHUNK_BYTES, CHUNK_BYTES, mb_full + 16);
        MBAR_EXPECT_TX(mb_full + 24, CHUNK_BYTES);
        bulk_cp(sb + SLOT_F * 4, cbb + 3 * (size_t)CHUNK_BYTES, CHUNK_BYTES,
                mb_full + 24);
    }

    float best[4] = {3.0e38f, 3.0e38f, 3.0e38f, 3.0e38f};
    int bidx[4] = {0, 0, 0, 0};

    float4* zb = (float4*)(out + (size_t)rowbase * Sq);
    const float4 zero4 = make_float4(0.0f, 0.0f, 0.0f, 0.0f);

    // Issue all 192 MMAs of one chunk into acc (zero-inited).
    auto chunk_mma = [&](float4 (&acc)[4][2], int s) {
        #pragma unroll
        for (int cb = 0; cb < 4; ++cb)
            #pragma unroll
            for (int t = 0; t < 2; ++t)
                acc[cb][t] = zero4;
        const float* Bbuf = sm + slot_f[s];
        const float* bn0 = Bbuf + g * RSTRIDE + m * 2;
        const float* bn1 = bn0 + 8 * RSTRIDE;
        const float* bn2 = bn0 + 16 * RSTRIDE;
        const float* bn3 = bn0 + 24 * RSTRIDE;
        #pragma unroll
        for (int kb = 0; kb < 8; ++kb) {
            float2 bh0 = *(const float2*)(bn0 + kb * 8);
            float2 bh1 = *(const float2*)(bn1 + kb * 8);
            float2 bh2 = *(const float2*)(bn2 + kb * 8);
            float2 bh3 = *(const float2*)(bn3 + kb * 8);
            float2 bl0 = *(const float2*)(bn0 + 64 + kb * 8);
            float2 bl1 = *(const float2*)(bn1 + 64 + kb * 8);
            float2 bl2 = *(const float2*)(bn2 + 64 + kb * 8);
            float2 bl3 = *(const float2*)(bn3 + 64 + kb * 8);
            mma1688(acc[0][0], Ah[0][kb][0], Ah[0][kb][1], bh0);
            mma1688(acc[0][1], Ah[1][kb][0], Ah[1][kb][1], bh0);
            mma1688(acc[1][0], Ah[0][kb][0], Ah[0][kb][1], bh1);
            mma1688(acc[1][1], Ah[1][kb][0], Ah[1][kb][1], bh1);
            mma1688(acc[2][0], Ah[0][kb][0], Ah[0][kb][1], bh2);
            mma1688(acc[2][1], Ah[1][kb][0], Ah[1][kb][1], bh2);
            mma1688(acc[3][0], Ah[0][kb][0], Ah[0][kb][1], bh3);
            mma1688(acc[3][1], Ah[1][kb][0], Ah[1][kb][1], bh3);
            mma1688(acc[0][0], Al[0][kb][0], Al[0][kb][1], bh0);
            mma1688(acc[0][1], Al[1][kb][0], Al[1][kb][1], bh0);
            mma1688(acc[1][0], Al[0][kb][0], Al[0][kb][1], bh1);
            mma1688(acc[1][1], Al[1][kb][0], Al[1][kb][1], bh1);
            mma1688(acc[2][0], Al[0][kb][0], Al[0][kb][1], bh2);
            mma1688(acc[2][1], Al[1][kb][0], Al[1][kb][1], bh2);
            mma1688(acc[3][0], Al[0][kb][0], Al[0][kb][1], bh3);
            mma1688(acc[3][1], Al[1][kb][0], Al[1][kb][1], bh3);
            mma1688(acc[0][0], Ah[0][kb][0], Ah[0][kb][1], bl0);
            mma1688(acc[0][1], Ah[1][kb][0], Ah[1][kb][1], bl0);
            mma1688(acc[1][0], Ah[0][kb][0], Ah[0][kb][1], bl1);
            mma1688(acc[1][1], Ah[1][kb][0], Ah[1][kb][1], bl1);
            mma1688(acc[2][0], Ah[0][kb][0], Ah[0][kb][1], bl2);
            mma1688(acc[2][1], Ah[1][kb][0], Ah[1][kb][1], bl2);
            mma1688(acc[3][0], Ah[0][kb][0], Ah[0][kb][1], bl3);
            mma1688(acc[3][1], Ah[1][kb][0], Ah[1][kb][1], bl3);
        }
    };

    // Deferred finish of chunk q: zero-fill slice, argmin, release slot,
    // refill slot with chunk q+4. Runs under the NEXT chunk's MMA shadow.
    auto chunk_finish = [&](float4 (&acc)[4][2], int q) {
        #pragma unroll
        for (int j = 0; j < 8; ++j)
            zb[q * 1024 + j * NTHR + tid] = zero4;
        #pragma unroll
        for (int cb = 0; cb < 4; ++cb) {
            int n0 = q * CH + cb * 8 + m * 2;
            float2 cv = *(const float2*)(sm + C2_F + n0);
            #pragma unroll
            for (int t = 0; t < 2; ++t) {
                int s0 = t * 2, s1 = t * 2 + 1;   // rows g, g+8 (per tile)
                float4 a = acc[cb][t];
                float sx = a.x + cv.x, sy = a.y + cv.y;
                float sz = a.z + cv.x, sw = a.w + cv.y;
                if (sx < best[s0]) { best[s0] = sx; bidx[s0] = n0; }
                if (sy < best[s0]) { best[s0] = sy; bidx[s0] = n0 + 1; }
                if (sz < best[s1]) { best[s1] = sz; bidx[s1] = n0; }
                if (sw < best[s1]) { best[s1] = sw; bidx[s1] = n0 + 1; }
            }
        }
        const int qs = q & 3;
        __syncwarp();
        if (lane == 0) MBAR_ARRIVE(mb_empty + 8 * qs);
        if (tid == 0 && q + 4 < NCHUNK) {
            const uint32_t phq = (uint32_t)((q >> 2) & 1);
            MBAR_WAIT(mb_empty + 8 * qs, phq);
            MBAR_EXPECT_TX(mb_full + 8 * qs, CHUNK_BYTES);
            bulk_cp(sb + slot_f[qs] * 4, cbb + (size_t)(q + 4) * CHUNK_BYTES,
                    CHUNK_BYTES, mb_full + 8 * qs);
        }
    };

    float4 accA[4][2], accB[4][2];

    MBAR_WAIT(mb_full + 0, 0);
    chunk_mma(accA, 0);
    #pragma unroll 1
    for (int p = 1; p < NCHUNK; ++p) {
        const int s = p & 3;
        const uint32_t ph = (uint32_t)((p >> 2) & 1);
        MBAR_WAIT(mb_full + 8 * s, ph);
        if (p & 1) {
            chunk_mma(accB, s);           // issue chunk p...
            chunk_finish(accA, p - 1);    // ...finish p-1 under its shadow
        } else {
            chunk_mma(accA, s);
            chunk_finish(accB, p - 1);
        }
    }
    chunk_finish(((NCHUNK - 1) & 1) ? accB : accA, NCHUNK - 1);

    // Reduce across the 4 lanes (m) sharing each row; tie -> smaller index.
    #pragma unroll
    for (int s = 0; s < 4; ++s) {
        #pragma unroll
        for (int o = 1; o <= 2; o <<= 1) {
            float ob = __shfl_xor_sync(0xFFFFFFFFu, best[s], o);
            int   oi = __shfl_xor_sync(0xFFFFFFFFu, bidx[s], o);
            if (ob < best[s] || (ob == best[s] && oi < bidx[s])) {
                best[s] = ob; bidx[s] = oi;
            }
        }
    }
    if (m == 0) {
        int* si = (int*)(sm + IDX_F);
        si[wb + g]          = bidx[0];
        si[wb + g + 8]      = bidx[1];
        si[wb + 16 + g]     = bidx[2];
        si[wb + 16 + g + 8] = bidx[3];
    }
    __syncthreads();

    // Final epilogue: one 4-byte 1.0f store per row (zeros already written;
    // __syncthreads orders them against these same-CTA stores).
    {
        const int* si = (const int*)(sm + IDX_F);
        out[(size_t)(rowbase + tid) * Sq + si[tid]] = 1.0f;
    }
}

// ---------------------------------------------------------------------------
extern "C" void kernel_launch(void* const* d_in, const int* in_sizes, int n_in,
                              void* d_out, int out_size) {
    const float* x       = (const float*)d_in[0];
    const float* c_sum   = (const float*)d_in[1];
    const float* c_count = (const float*)d_in[2];
    float* out   = (float*)d_out;
    float* out_c = out + ONEHOT_ELEMS;

    (void)in_sizes; (void)n_in; (void)out_size;

    cudaFuncSetAttribute(vq_kernel,
                         cudaFuncAttributeMaxDynamicSharedMemorySize,
                         SMEM_TOTAL);

    prep_kernel<<<Hq * Sq, 32>>>(c_sum, c_count, out_c);
    vq_kernel<<<(Bq * Hq * Lq) / ROWS, NTHR, SMEM_TOTAL>>>(x, out);
}

// round 16
// speedup vs baseline: 1.0915x; 1.0915x over previous
#include <cuda_runtime.h>
#include <cstdint>

// Quantizer — VQ assignment via mma.sync tf32 3-term split (sm_100-safe PTX).
//   x [B,H,L,D] f32, c_sum [H,S,D] f32, c_count [H,S] f32
//   out = [delta_onehot [B,H,L,S] f32 | c [H,S,D] f32]
// score_s = |c_s|^2 + x.(-2 c_s); 3-term tf32 split, fp32 accumulate
// (residual ~1e-5 << argmin gaps; rel_err 0.0 R7-R15).
// R14 -> R16: 3 CTAs/SM (ROWS 64, warp tile M=16 -> ~150 regs, 72KB smem)
// so 3 uncorrelated warps per SMSP cover each other's serial tails
// (R15 showed in-warp overlap via ping-pong costs too many regs). Also:
// B slot released right after the MMA-issue loop (slot LDS provably done),
// so the refill overlaps the argmin tail.

#define Bq 4
#define Hq 16
#define Lq 4096
#define Dq 64
#define Sq 512
#define ONEHOT_ELEMS ((size_t)Bq * Hq * Lq * Sq)

#define ROWS 64
#define NTHR 128
#define CH   32
#define RSTRIDE 136                        // padded row (floats)
#define SLOT_F  (CH * RSTRIDE)             // 4352 floats = 17408 B per chunk
#define CHUNK_BYTES (SLOT_F * 4)
#define NCHUNK  (Sq / CH)                  // 16

// Codebook scratch, PRE-PADDED chunk layout: per (h,chunk): 32 rows x
// [hi 64 | lo 64 | pad 8] floats, rows k-permuted for mma B fragments.
__device__ float g_cbB[Hq * NCHUNK * SLOT_F];   // ~4.5 MB
__device__ float g_c2[Hq * Sq];                 // 32 KB

// -------------------- helpers --------------------
__device__ __forceinline__ uint32_t smem_u32(const void* p) {
    uint32_t a;
    asm("{ .reg .u64 t; cvta.to.shared.u64 t, %1; cvt.u32.u64 %0, t; }"
        : "=r"(a) : "l"(p));
    return a;
}
__device__ __forceinline__ float to_tf32(float x) {
    uint32_t u;
    asm("cvt.rna.tf32.f32 %0, %1;" : "=r"(u) : "f"(x));
    return __uint_as_float(u);
}

#define MBAR_INIT(a, n) \
    asm volatile("mbarrier.init.shared.b64 [%0], %1;" :: "r"(a), "r"(n) : "memory")
#define MBAR_EXPECT_TX(a, tx) \
    asm volatile("mbarrier.arrive.expect_tx.shared.b64 _, [%0], %1;" \
                 :: "r"(a), "r"(tx) : "memory")
#define MBAR_ARRIVE(a) \
    asm volatile("mbarrier.arrive.shared.b64 _, [%0];" :: "r"(a) : "memory")
#define MBAR_WAIT(a, ph) do {                                              \
    uint32_t _m = (a), _p = (ph), _d;                                      \
    asm volatile("{\n\t.reg .pred p;\n\t"                                  \
        "mbarrier.try_wait.parity.acquire.cta.shared::cta.b64 p, [%1], %2;\n\t" \
        "selp.b32 %0, 1, 0, p;\n\t}" : "=r"(_d) : "r"(_m), "r"(_p) : "memory"); \
    if (!_d) {                                                             \
        asm volatile("{\n\t.reg .pred P1;\n\tWL%=:\n\t"                    \
            "mbarrier.try_wait.parity.acquire.cta.shared::cta.b64 P1, [%0], %1, 0x989680;\n\t" \
            "@P1 bra.uni WD%=;\n\tbra.uni WL%=;\n\tWD%=:\n\t}"             \
            :: "r"(_m), "r"(_p) : "memory");                               \
    }                                                                      \
} while (0)

__device__ __forceinline__ void bulk_cp(uint32_t dst, const void* src,
                                        uint32_t bytes, uint32_t mbar) {
    asm volatile(
        "cp.async.bulk.shared::cta.global.mbarrier::complete_tx::bytes "
        "[%0], [%1], %2, [%3];"
        :: "r"(dst), "l"(src), "r"(bytes), "r"(mbar) : "memory");
}

// m16n8k8 tf32 row.col; operand mapping verified R6-R15 (rel_err 0.0).
__device__ __forceinline__ void mma1688(float4& d, float2 a0, float2 a1, float2 b) {
    asm("mma.sync.aligned.m16n8k8.row.col.f32.tf32.tf32.f32 "
        "{%0,%1,%2,%3}, {%4,%5,%6,%7}, {%8,%9}, {%0,%1,%2,%3};"
        : "+f"(d.x), "+f"(d.y), "+f"(d.z), "+f"(d.w)
        : "r"(__float_as_uint(a0.x)), "r"(__float_as_uint(a1.x)),
          "r"(__float_as_uint(a0.y)), "r"(__float_as_uint(a1.y)),
          "r"(__float_as_uint(b.x)),  "r"(__float_as_uint(b.y)));
}

// k-permutation: pos(k) puts (m, m+4) adjacent within each 8-block.
__device__ __forceinline__ int kpos(int k) {
    return (k & ~7) + ((k & 3) << 1) + ((k >> 2) & 1);
}

// -------------------- prep --------------------
__global__ void prep_kernel(const float* __restrict__ c_sum,
                            const float* __restrict__ c_count,
                            float* __restrict__ out_c) {
    const int cw = blockIdx.x;            // h*S + s
    const int lane = threadIdx.x;         // 2 dims per lane
    const int h = cw >> 9, s = cw & 511;
    float cnt = fmaxf(c_count[cw], 1e-6f);

    float2 v = ((const float2*)(c_sum + (size_t)cw * Dq))[lane];
    float a = v.x / cnt;                  // IEEE divide: matches reference
    float b = v.y / cnt;
    ((float2*)(out_c + (size_t)cw * Dq))[lane] = make_float2(a, b);

    float* row = g_cbB + ((size_t)(h * NCHUNK + (s >> 5)) * SLOT_F)
                       + (size_t)(s & 31) * RSTRIDE;
    int k0 = 2 * lane, k1 = 2 * lane + 1;
    float m0 = -2.0f * a, m1 = -2.0f * b;
    float h0 = to_tf32(m0), h1 = to_tf32(m1);
    row[kpos(k0)]      = h0;
    row[kpos(k1)]      = h1;
    row[64 + kpos(k0)] = to_tf32(m0 - h0);
    row[64 + kpos(k1)] = to_tf32(m1 - h1);

    float sq = a * a + b * b;
    #pragma unroll
    for (int o = 16; o > 0; o >>= 1) sq += __shfl_xor_sync(0xFFFFFFFFu, sq, o);
    if (lane == 0) g_c2[cw] = sq;
}

// -------------------- main --------------------
// CTA: 128 threads (4 warps), 64 rows, 3 CTAs/SM. Warp tile M=16, A hi/lo in
// registers. B: 4-slot ring (slots 2,3 occupy the dead A-staging region,
// which is exactly 2 slots), bulk-copy filled, mbarrier producer/consumer.
#define AREG_F  (ROWS * RSTRIDE)      // 8704 floats = exactly 2 slots
#define B0_F    AREG_F                // slot 0: 8704
#define B1_F    (B0_F + SLOT_F)      // slot 1: 13056
#define C2_F    (B1_F + SLOT_F)      // 17408
#define IDX_F   (C2_F + Sq)          // 17920
#define MBAR_F  (IDX_F + ROWS)       // 17984 (17984*4 % 16 == 0)
#define SMEM_TOTAL (MBAR_F * 4 + 64)  // 72000 B -> 3 CTAs/SM

__global__ __launch_bounds__(NTHR, 3)
void vq_kernel(const float* __restrict__ x, float* __restrict__ out) {
    extern __shared__ float sm[];
    const uint32_t sb = smem_u32(sm);
    const int tid = threadIdx.x;
    const int wid = tid >> 5, lane = tid & 31;
    const int g = lane >> 2, m = lane & 3;
    const int wrow = wid * 16;

    const int rowbase = blockIdx.x * ROWS;
    const int h = (blockIdx.x >> 6) & (Hq - 1);   // 64 CTAs per (b,h)
    const char* cbb = (const char*)(g_cbB + (size_t)h * NCHUNK * SLOT_F);

    const uint32_t slot_f[4] = {B0_F, B1_F, 0u, SLOT_F};
    const uint32_t mb_full  = sb + MBAR_F * 4;         // 4 x 8B
    const uint32_t mb_empty = mb_full + 32;            // 4 x 8B

    if (tid == 0) {
        #pragma unroll
        for (int i = 0; i < 4; ++i) {
            MBAR_INIT(mb_full + 8 * i, 1);
            MBAR_INIT(mb_empty + 8 * i, 4);
        }
    }
    __syncthreads();                       // barrier init visible

    // Producer prologue: chunks 0,1 -> slots 0,1 (disjoint from A region).
    if (tid == 0) {
        MBAR_EXPECT_TX(mb_full + 0, CHUNK_BYTES);
        bulk_cp(sb + B0_F * 4, cbb, CHUNK_BYTES, mb_full + 0);
        MBAR_EXPECT_TX(mb_full + 8, CHUNK_BYTES);
        bulk_cp(sb + B1_F * 4, cbb + CHUNK_BYTES, CHUNK_BYTES, mb_full + 8);
    }

    // Stage c2 + A tile (hi/lo tf32, k-permuted, padded rows).
    for (int i = tid; i < Sq; i += NTHR) sm[C2_F + i] = g_c2[h * Sq + i];
    {
        const float4* xb = (const float4*)(x + (size_t)rowbase * Dq);
        #pragma unroll
        for (int it = 0; it < 4; ++it) {
            int i = it * NTHR + tid;          // 64 rows x 8 kblocks
            int r = i >> 3, kb = i & 7;
            float4 v0 = xb[r * 16 + kb * 2];
            float4 v1 = xb[r * 16 + kb * 2 + 1];
            float h0 = to_tf32(v0.x), h1 = to_tf32(v0.y),
                  h2 = to_tf32(v0.z), h3 = to_tf32(v0.w),
                  h4 = to_tf32(v1.x), h5 = to_tf32(v1.y),
                  h6 = to_tf32(v1.z), h7 = to_tf32(v1.w);
            float l0 = to_tf32(v0.x - h0), l1 = to_tf32(v0.y - h1),
                  l2 = to_tf32(v0.z - h2), l3 = to_tf32(v0.w - h3),
                  l4 = to_tf32(v1.x - h4), l5 = to_tf32(v1.y - h5),
                  l6 = to_tf32(v1.z - h6), l7 = to_tf32(v1.w - h7);
            float* dh = sm + r * RSTRIDE + kb * 8;
            ((float4*)dh)[0] = make_float4(h0, h4, h1, h5);
            ((float4*)dh)[1] = make_float4(h2, h6, h3, h7);
            float* dl = dh + 64;
            ((float4*)dl)[0] = make_float4(l0, l4, l1, l5);
            ((float4*)dl)[1] = make_float4(l2, l6, l3, l7);
        }
    }
    __syncthreads();

    // A fragments to registers: [kblock][row-half], hi and lo (M=16).
    float2 Ah[8][2], Al[8][2];
    #pragma unroll
    for (int kb = 0; kb < 8; ++kb) {
        const float* b0 = sm + (wrow + g) * RSTRIDE + kb * 8 + m * 2;
        const float* b8 = b0 + 8 * RSTRIDE;
        Ah[kb][0] = *(const float2*)b0;
        Ah[kb][1] = *(const float2*)b8;
        Al[kb][0] = *(const float2*)(b0 + 64);
        Al[kb][1] = *(const float2*)(b8 + 64);
    }
    __syncthreads();   // A region dead -> slots 2,3 may be filled

    if (tid == 0) {
        MBAR_EXPECT_TX(mb_full + 16, CHUNK_BYTES);
        bulk_cp(sb + 0, cbb + 2 * (size_t)CHUNK_BYTES, CHUNK_BYTES, mb_full + 16);
        MBAR_EXPECT_TX(mb_full + 24, CHUNK_BYTES);
        bulk_cp(sb + SLOT_F * 4, cbb + 3 * (size_t)CHUNK_BYTES, CHUNK_BYTES,
                mb_full + 24);
    }

    float best[2] = {3.0e38f, 3.0e38f};    // rows g, g+8 of this warp's tile
    int bidx[2] = {0, 0};

    float4* zb = (float4*)(out + (size_t)rowbase * Sq);
    const float4 zero4 = make_float4(0.0f, 0.0f, 0.0f, 0.0f);

    // Mainloop: wait full -> 96 MMAs -> release slot (slot LDS complete once
    // last dependent MMA issued) -> refill overlaps zero-fill/argmin tail.
    for (int p = 0; p < NCHUNK; ++p) {
        const int s = p & 3;
        const uint32_t ph = (uint32_t)((p >> 2) & 1);
        MBAR_WAIT(mb_full + 8 * s, ph);

        const float* Bbuf = sm + slot_f[s];

        float4 acc[4];                    // 4 colblocks -> 4 indep chains
        #pragma unroll
        for (int cb = 0; cb < 4; ++cb) acc[cb] = zero4;

        const float* bn0 = Bbuf + g * RSTRIDE + m * 2;
        const float* bn1 = bn0 + 8 * RSTRIDE;
        const float* bn2 = bn0 + 16 * RSTRIDE;
        const float* bn3 = bn0 + 24 * RSTRIDE;
        #pragma unroll
        for (int kb = 0; kb < 8; ++kb) {
            float2 bh0 = *(const float2*)(bn0 + kb * 8);
            float2 bh1 = *(const float2*)(bn1 + kb * 8);
            float2 bh2 = *(const float2*)(bn2 + kb * 8);
            float2 bh3 = *(const float2*)(bn3 + kb * 8);
            float2 bl0 = *(const float2*)(bn0 + 64 + kb * 8);
            float2 bl1 = *(const float2*)(bn1 + 64 + kb * 8);
            float2 bl2 = *(const float2*)(bn2 + 64 + kb * 8);
            float2 bl3 = *(const float2*)(bn3 + 64 + kb * 8);
            // term hi*hi
            mma1688(acc[0], Ah[kb][0], Ah[kb][1], bh0);
            mma1688(acc[1], Ah[kb][0], Ah[kb][1], bh1);
            mma1688(acc[2], Ah[kb][0], Ah[kb][1], bh2);
            mma1688(acc[3], Ah[kb][0], Ah[kb][1], bh3);
            // term lo*hi
            mma1688(acc[0], Al[kb][0], Al[kb][1], bh0);
            mma1688(acc[1], Al[kb][0], Al[kb][1], bh1);
            mma1688(acc[2], Al[kb][0], Al[kb][1], bh2);
            mma1688(acc[3], Al[kb][0], Al[kb][1], bh3);
            // term hi*lo
            mma1688(acc[0], Ah[kb][0], Ah[kb][1], bl0);
            mma1688(acc[1], Ah[kb][0], Ah[kb][1], bl1);
            mma1688(acc[2], Ah[kb][0], Ah[kb][1], bl2);
            mma1688(acc[3], Ah[kb][0], Ah[kb][1], bl3);
        }

        // Early slot release: all LDS from this slot completed (their
        // dependent MMAs issued). Refill overlaps the tail below.
        __syncwarp();
        if (lane == 0) MBAR_ARRIVE(mb_empty + 8 * s);
        if (tid == 0 && p + 4 < NCHUNK) {
            MBAR_WAIT(mb_empty + 8 * s, ph);
            MBAR_EXPECT_TX(mb_full + 8 * s, CHUNK_BYTES);
            bulk_cp(sb + slot_f[s] * 4, cbb + (size_t)(p + 4) * CHUNK_BYTES,
                    CHUNK_BYTES, mb_full + 8 * s);
        }

        // Zero-fill 1/16 of the one-hot block (by rows; coalesced STG.128).
        #pragma unroll
        for (int j = 0; j < 4; ++j)
            zb[p * 512 + j * NTHR + tid] = zero4;

        // Argmin (ascending n, strict '<' = first-min, jnp.argmin);
        // c2 added here instead of acc-init.
        #pragma unroll
        for (int cb = 0; cb < 4; ++cb) {
            int n0 = p * CH + cb * 8 + m * 2;
            float2 cv = *(const float2*)(sm + C2_F + n0);
            float4 a = acc[cb];
            float sx = a.x + cv.x, sy = a.y + cv.y;   // row g
            float sz = a.z + cv.x, sw = a.w + cv.y;   // row g+8
            if (sx < best[0]) { best[0] = sx; bidx[0] = n0; }
            if (sy < best[0]) { best[0] = sy; bidx[0] = n0 + 1; }
            if (sz < best[1]) { best[1] = sz; bidx[1] = n0; }
            if (sw < best[1]) { best[1] = sw; bidx[1] = n0 + 1; }
        }
    }

    // Reduce across the 4 lanes (m) sharing each row; tie -> smaller index.
    #pragma unroll
    for (int s = 0; s < 2; ++s) {
        #pragma unroll
        for (int o = 1; o <= 2; o <<= 1) {
            float ob = __shfl_xor_sync(0xFFFFFFFFu, best[s], o);
            int   oi = __shfl_xor_sync(0xFFFFFFFFu, bidx[s], o);
            if (ob < best[s] || (ob == best[s] && oi < bidx[s])) {
                best[s] = ob; bidx[s] = oi;
            }
        }
    }
    if (m == 0) {
        int* si = (int*)(sm + IDX_F);
        si[wrow + g]     = bidx[0];
        si[wrow + g + 8] = bidx[1];
    }
    __syncthreads();

    // Final epilogue: one 4-byte 1.0f store per row (zeros already written;
    // __syncthreads orders them against these same-CTA stores).
    if (tid < ROWS) {
        const int* si = (const int*)(sm + IDX_F);
        out[(size_t)(rowbase + tid) * Sq + si[tid]] = 1.0f;
    }
}

// ---------------------------------------------------------------------------
extern "C" void kernel_launch(void* const* d_in, const int* in_sizes, int n_in,
                              void* d_out, int out_size) {
    const float* x       = (const float*)d_in[0];
    const float* c_sum   = (const float*)d_in[1];
    const float* c_count = (const float*)d_in[2];
    float* out   = (float*)d_out;
    float* out_c = out + ONEHOT_ELEMS;

    (void)in_sizes; (void)n_in; (void)out_size;

    cudaFuncSetAttribute(vq_kernel,
                         cudaFuncAttributeMaxDynamicSharedMemorySize,
                         SMEM_TOTAL);

    prep_kernel<<<Hq * Sq, 32>>>(c_sum, c_count, out_c);
    vq_kernel<<<(Bq * Hq * Lq) / ROWS, NTHR, SMEM_TOTAL>>>(x, out);
}

// round 17
// speedup vs baseline: 1.1554x; 1.0585x over previous
#include <cuda_runtime.h>
#include <cstdint>

// Quantizer — VQ assignment via mma.sync tf32 3-term split (sm_100-safe PTX).
//   x [B,H,L,D] f32, c_sum [H,S,D] f32, c_count [H,S] f32
//   out = [delta_onehot [B,H,L,S] f32 | c [H,S,D] f32]
// score_s = |c_s|^2 + x.(-2 c_s); 3-term tf32 split, fp32 accumulate
// (residual ~1e-5 << argmin gaps; rel_err 0.0 R7-R16).
// R16 -> R17: 4 CTAs/SM. R16 showed L1(71%) and tensor(72%) co-limiting
// with regs at 117 -- a 4th warp/SMSP scales both pipes together. smem cut
// 72KB -> 54.6KB by using a 3-slot B ring (slot 0 outside the A-staging
// region; slots 1,2 inside it once A is register-resident).

#define Bq 4
#define Hq 16
#define Lq 4096
#define Dq 64
#define Sq 512
#define ONEHOT_ELEMS ((size_t)Bq * Hq * Lq * Sq)

#define ROWS 64
#define NTHR 128
#define CH   32
#define RSTRIDE 136                        // padded row (floats)
#define SLOT_F  (CH * RSTRIDE)             // 4352 floats = 17408 B per chunk
#define CHUNK_BYTES (SLOT_F * 4)
#define NCHUNK  (Sq / CH)                  // 16

// Codebook scratch, PRE-PADDED chunk layout: per (h,chunk): 32 rows x
// [hi 64 | lo 64 | pad 8] floats, rows k-permuted for mma B fragments.
__device__ float g_cbB[Hq * NCHUNK * SLOT_F];   // ~4.5 MB
__device__ float g_c2[Hq * Sq];                 // 32 KB

// -------------------- helpers --------------------
__device__ __forceinline__ uint32_t smem_u32(const void* p) {
    uint32_t a;
    asm("{ .reg .u64 t; cvta.to.shared.u64 t, %1; cvt.u32.u64 %0, t; }"
        : "=r"(a) : "l"(p));
    return a;
}
__device__ __forceinline__ float to_tf32(float x) {
    uint32_t u;
    asm("cvt.rna.tf32.f32 %0, %1;" : "=r"(u) : "f"(x));
    return __uint_as_float(u);
}

#define MBAR_INIT(a, n) \
    asm volatile("mbarrier.init.shared.b64 [%0], %1;" :: "r"(a), "r"(n) : "memory")
#define MBAR_EXPECT_TX(a, tx) \
    asm volatile("mbarrier.arrive.expect_tx.shared.b64 _, [%0], %1;" \
                 :: "r"(a), "r"(tx) : "memory")
#define MBAR_ARRIVE(a) \
    asm volatile("mbarrier.arrive.shared.b64 _, [%0];" :: "r"(a) : "memory")
#define MBAR_WAIT(a, ph) do {                                              \
    uint32_t _m = (a), _p = (ph), _d;                                      \
    asm volatile("{\n\t.reg .pred p;\n\t"                                  \
        "mbarrier.try_wait.parity.acquire.cta.shared::cta.b64 p, [%1], %2;\n\t" \
        "selp.b32 %0, 1, 0, p;\n\t}" : "=r"(_d) : "r"(_m), "r"(_p) : "memory"); \
    if (!_d) {                                                             \
        asm volatile("{\n\t.reg .pred P1;\n\tWL%=:\n\t"                    \
            "mbarrier.try_wait.parity.acquire.cta.shared::cta.b64 P1, [%0], %1, 0x989680;\n\t" \
            "@P1 bra.uni WD%=;\n\tbra.uni WL%=;\n\tWD%=:\n\t}"             \
            :: "r"(_m), "r"(_p) : "memory");                               \
    }                                                                      \
} while (0)

__device__ __forceinline__ void bulk_cp(uint32_t dst, const void* src,
                                        uint32_t bytes, uint32_t mbar) {
    asm volatile(
        "cp.async.bulk.shared::cta.global.mbarrier::complete_tx::bytes "
        "[%0], [%1], %2, [%3];"
        :: "r"(dst), "l"(src), "r"(bytes), "r"(mbar) : "memory");
}

// m16n8k8 tf32 row.col; operand mapping verified R6-R16 (rel_err 0.0).
__device__ __forceinline__ void mma1688(float4& d, float2 a0, float2 a1, float2 b) {
    asm("mma.sync.aligned.m16n8k8.row.col.f32.tf32.tf32.f32 "
        "{%0,%1,%2,%3}, {%4,%5,%6,%7}, {%8,%9}, {%0,%1,%2,%3};"
        : "+f"(d.x), "+f"(d.y), "+f"(d.z), "+f"(d.w)
        : "r"(__float_as_uint(a0.x)), "r"(__float_as_uint(a1.x)),
          "r"(__float_as_uint(a0.y)), "r"(__float_as_uint(a1.y)),
          "r"(__float_as_uint(b.x)),  "r"(__float_as_uint(b.y)));
}

// k-permutation: pos(k) puts (m, m+4) adjacent within each 8-block.
__device__ __forceinline__ int kpos(int k) {
    return (k & ~7) + ((k & 3) << 1) + ((k >> 2) & 1);
}

// -------------------- prep --------------------
__global__ void prep_kernel(const float* __restrict__ c_sum,
                            const float* __restrict__ c_count,
                            float* __restrict__ out_c) {
    const int cw = blockIdx.x;            // h*S + s
    const int lane = threadIdx.x;         // 2 dims per lane
    const int h = cw >> 9, s = cw & 511;
    float cnt = fmaxf(c_count[cw], 1e-6f);

    float2 v = ((const float2*)(c_sum + (size_t)cw * Dq))[lane];
    float a = v.x / cnt;                  // IEEE divide: matches reference
    float b = v.y / cnt;
    ((float2*)(out_c + (size_t)cw * Dq))[lane] = make_float2(a, b);

    float* row = g_cbB + ((size_t)(h * NCHUNK + (s >> 5)) * SLOT_F)
                       + (size_t)(s & 31) * RSTRIDE;
    int k0 = 2 * lane, k1 = 2 * lane + 1;
    float m0 = -2.0f * a, m1 = -2.0f * b;
    float h0 = to_tf32(m0), h1 = to_tf32(m1);
    row[kpos(k0)]      = h0;
    row[kpos(k1)]      = h1;
    row[64 + kpos(k0)] = to_tf32(m0 - h0);
    row[64 + kpos(k1)] = to_tf32(m1 - h1);

    float sq = a * a + b * b;
    #pragma unroll
    for (int o = 16; o > 0; o >>= 1) sq += __shfl_xor_sync(0xFFFFFFFFu, sq, o);
    if (lane == 0) g_c2[cw] = sq;
}

// -------------------- main --------------------
// CTA: 128 threads (4 warps), 64 rows, 4 CTAs/SM. Warp tile M=16, A hi/lo in
// registers. B: 3-slot ring (slot 0 outside A-staging; slots 1,2 inside it,
// filled after A is register-resident), bulk-copy + mbarrier prod/consumer.
#define AREG_F  (ROWS * RSTRIDE)      // 8704 floats = exactly 2 slots
#define S0_F    AREG_F                // slot 0: 8704  (outside A region)
#define S1_F    0                     // slot 1: 0     (A region)
#define S2_F    SLOT_F                // slot 2: 4352  (A region)
#define C2_F    (AREG_F + SLOT_F)     // 13056
#define IDX_F   (C2_F + Sq)           // 13568
#define MBAR_F  (IDX_F + ROWS)        // 13632 (13632*4 % 16 == 0)
#define SMEM_TOTAL (MBAR_F * 4 + 64)  // 54592 B -> 4 CTAs/SM

__global__ __launch_bounds__(NTHR, 4)
void vq_kernel(const float* __restrict__ x, float* __restrict__ out) {
    extern __shared__ float sm[];
    const uint32_t sb = smem_u32(sm);
    const int tid = threadIdx.x;
    const int wid = tid >> 5, lane = tid & 31;
    const int g = lane >> 2, m = lane & 3;
    const int wrow = wid * 16;

    const int rowbase = blockIdx.x * ROWS;
    const int h = (blockIdx.x >> 6) & (Hq - 1);   // 64 CTAs per (b,h)
    const char* cbb = (const char*)(g_cbB + (size_t)h * NCHUNK * SLOT_F);

    const uint32_t slot_f[3] = {S0_F, S1_F, S2_F};
    const uint32_t mb_full  = sb + MBAR_F * 4;         // 3 x 8B
    const uint32_t mb_empty = mb_full + 24;            // 3 x 8B

    if (tid == 0) {
        #pragma unroll
        for (int i = 0; i < 3; ++i) {
            MBAR_INIT(mb_full + 8 * i, 1);
            MBAR_INIT(mb_empty + 8 * i, 4);
        }
    }
    __syncthreads();                       // barrier init visible

    // Producer prologue: chunk 0 -> slot 0 (disjoint from A region).
    if (tid == 0) {
        MBAR_EXPECT_TX(mb_full + 0, CHUNK_BYTES);
        bulk_cp(sb + S0_F * 4, cbb, CHUNK_BYTES, mb_full + 0);
    }

    // Stage c2 + A tile (hi/lo tf32, k-permuted, padded rows).
    for (int i = tid; i < Sq; i += NTHR) sm[C2_F + i] = g_c2[h * Sq + i];
    {
        const float4* xb = (const float4*)(x + (size_t)rowbase * Dq);
        #pragma unroll
        for (int it = 0; it < 4; ++it) {
            int i = it * NTHR + tid;          // 64 rows x 8 kblocks
            int r = i >> 3, kb = i & 7;
            float4 v0 = xb[r * 16 + kb * 2];
            float4 v1 = xb[r * 16 + kb * 2 + 1];
            float h0 = to_tf32(v0.x), h1 = to_tf32(v0.y),
                  h2 = to_tf32(v0.z), h3 = to_tf32(v0.w),
                  h4 = to_tf32(v1.x), h5 = to_tf32(v1.y),
                  h6 = to_tf32(v1.z), h7 = to_tf32(v1.w);
            float l0 = to_tf32(v0.x - h0), l1 = to_tf32(v0.y - h1),
                  l2 = to_tf32(v0.z - h2), l3 = to_tf32(v0.w - h3),
                  l4 = to_tf32(v1.x - h4), l5 = to_tf32(v1.y - h5),
                  l6 = to_tf32(v1.z - h6), l7 = to_tf32(v1.w - h7);
            float* dh = sm + r * RSTRIDE + kb * 8;
            ((float4*)dh)[0] = make_float4(h0, h4, h1, h5);
            ((float4*)dh)[1] = make_float4(h2, h6, h3, h7);
            float* dl = dh + 64;
            ((float4*)dl)[0] = make_float4(l0, l4, l1, l5);
            ((float4*)dl)[1] = make_float4(l2, l6, l3, l7);
        }
    }
    __syncthreads();

    // A fragments to registers: [kblock][row-half], hi and lo (M=16).
    float2 Ah[8][2], Al[8][2];
    #pragma unroll
    for (int kb = 0; kb < 8; ++kb) {
        const float* b0 = sm + (wrow + g) * RSTRIDE + kb * 8 + m * 2;
        const float* b8 = b0 + 8 * RSTRIDE;
        Ah[kb][0] = *(const float2*)b0;
        Ah[kb][1] = *(const float2*)b8;
        Al[kb][0] = *(const float2*)(b0 + 64);
        Al[kb][1] = *(const float2*)(b8 + 64);
    }
    __syncthreads();   // A region dead -> slots 1,2 may be filled

    if (tid == 0) {
        MBAR_EXPECT_TX(mb_full + 8, CHUNK_BYTES);
        bulk_cp(sb + S1_F * 4, cbb + 1 * (size_t)CHUNK_BYTES, CHUNK_BYTES,
                mb_full + 8);
        MBAR_EXPECT_TX(mb_full + 16, CHUNK_BYTES);
        bulk_cp(sb + S2_F * 4, cbb + 2 * (size_t)CHUNK_BYTES, CHUNK_BYTES,
                mb_full + 16);
    }

    float best[2] = {3.0e38f, 3.0e38f};    // rows g, g+8 of this warp's tile
    int bidx[2] = {0, 0};

    float4* zb = (float4*)(out + (size_t)rowbase * Sq);
    const float4 zero4 = make_float4(0.0f, 0.0f, 0.0f, 0.0f);

    // Mainloop: chunk p -> slot p%3, phase (p/3)&1 (increment-based mod-3).
    int s = 0;
    uint32_t ph = 0;
    for (int p = 0; p < NCHUNK; ++p) {
        MBAR_WAIT(mb_full + 8 * s, ph);

        const float* Bbuf = sm + slot_f[s];

        float4 acc[4];                    // 4 colblocks -> 4 indep chains
        #pragma unroll
        for (int cb = 0; cb < 4; ++cb) acc[cb] = zero4;

        const float* bn0 = Bbuf + g * RSTRIDE + m * 2;
        const float* bn1 = bn0 + 8 * RSTRIDE;
        const float* bn2 = bn0 + 16 * RSTRIDE;
        const float* bn3 = bn0 + 24 * RSTRIDE;
        #pragma unroll
        for (int kb = 0; kb < 8; ++kb) {
            float2 bh0 = *(const float2*)(bn0 + kb * 8);
            float2 bh1 = *(const float2*)(bn1 + kb * 8);
            float2 bh2 = *(const float2*)(bn2 + kb * 8);
            float2 bh3 = *(const float2*)(bn3 + kb * 8);
            float2 bl0 = *(const float2*)(bn0 + 64 + kb * 8);
            float2 bl1 = *(const float2*)(bn1 + 64 + kb * 8);
            float2 bl2 = *(const float2*)(bn2 + 64 + kb * 8);
            float2 bl3 = *(const float2*)(bn3 + 64 + kb * 8);
            // term hi*hi
            mma1688(acc[0], Ah[kb][0], Ah[kb][1], bh0);
            mma1688(acc[1], Ah[kb][0], Ah[kb][1], bh1);
            mma1688(acc[2], Ah[kb][0], Ah[kb][1], bh2);
            mma1688(acc[3], Ah[kb][0], Ah[kb][1], bh3);
            // term lo*hi
            mma1688(acc[0], Al[kb][0], Al[kb][1], bh0);
            mma1688(acc[1], Al[kb][0], Al[kb][1], bh1);
            mma1688(acc[2], Al[kb][0], Al[kb][1], bh2);
            mma1688(acc[3], Al[kb][0], Al[kb][1], bh3);
            // term hi*lo
            mma1688(acc[0], Ah[kb][0], Ah[kb][1], bl0);
            mma1688(acc[1], Ah[kb][0], Ah[kb][1], bl1);
            mma1688(acc[2], Ah[kb][0], Ah[kb][1], bl2);
            mma1688(acc[3], Ah[kb][0], Ah[kb][1], bl3);
        }

        // Early slot release: all LDS from this slot completed (their
        // dependent MMAs issued). Refill overlaps the tail below.
        __syncwarp();
        if (lane == 0) MBAR_ARRIVE(mb_empty + 8 * s);
        if (tid == 0 && p + 3 < NCHUNK) {
            MBAR_WAIT(mb_empty + 8 * s, ph);
            MBAR_EXPECT_TX(mb_full + 8 * s, CHUNK_BYTES);
            bulk_cp(sb + slot_f[s] * 4, cbb + (size_t)(p + 3) * CHUNK_BYTES,
                    CHUNK_BYTES, mb_full + 8 * s);
        }

        // Zero-fill 1/16 of the one-hot block (coalesced STG.128).
        #pragma unroll
        for (int j = 0; j < 4; ++j)
            zb[p * 512 + j * NTHR + tid] = zero4;

        // Argmin (ascending n, strict '<' = first-min, jnp.argmin);
        // c2 added here instead of acc-init.
        #pragma unroll
        for (int cb = 0; cb < 4; ++cb) {
            int n0 = p * CH + cb * 8 + m * 2;
            float2 cv = *(const float2*)(sm + C2_F + n0);
            float4 a = acc[cb];
            float sx = a.x + cv.x, sy = a.y + cv.y;   // row g
            float sz = a.z + cv.x, sw = a.w + cv.y;   // row g+8
            if (sx < best[0]) { best[0] = sx; bidx[0] = n0; }
            if (sy < best[0]) { best[0] = sy; bidx[0] = n0 + 1; }
            if (sz < best[1]) { best[1] = sz; bidx[1] = n0; }
            if (sw < best[1]) { best[1] = sw; bidx[1] = n0 + 1; }
        }

        if (++s == 3) { s = 0; ph ^= 1; }
    }

    // Reduce across the 4 lanes (m) sharing each row; tie -> smaller index.
    #pragma unroll
    for (int t = 0; t < 2; ++t) {
        #pragma unroll
        for (int o = 1; o <= 2; o <<= 1) {
            float ob = __shfl_xor_sync(0xFFFFFFFFu, best[t], o);
            int   oi = __shfl_xor_sync(0xFFFFFFFFu, bidx[t], o);
            if (ob < best[t] || (ob == best[t] && oi < bidx[t])) {
                best[t] = ob; bidx[t] = oi;
            }
        }
    }
    if (m == 0) {
        int* si = (int*)(sm + IDX_F);
        si[wrow + g]     = bidx[0];
        si[wrow + g + 8] = bidx[1];
    }
    __syncthreads();

    // Final epilogue: one 4-byte 1.0f store per row (zeros already written;
    // __syncthreads orders them against these same-CTA stores).
    if (tid < ROWS) {
        const int* si = (const int*)(sm + IDX_F);
        out[(size_t)(rowbase + tid) * Sq + si[tid]] = 1.0f;
    }
}

// ---------------------------------------------------------------------------
extern "C" void kernel_launch(void* const* d_in, const int* in_sizes, int n_in,
                              void* d_out, int out_size) {
    const float* x       = (const float*)d_in[0];
    const float* c_sum   = (const float*)d_in[1];
    const float* c_count = (const float*)d_in[2];
    float* out   = (float*)d_out;
    float* out_c = out + ONEHOT_ELEMS;

    (void)in_sizes; (void)n_in; (void)out_size;

    cudaFuncSetAttribute(vq_kernel,
                         cudaFuncAttributeMaxDynamicSharedMemorySize,
                         SMEM_TOTAL);

    prep_kernel<<<Hq * Sq, 32>>>(c_sum, c_count, out_c);
    vq_kernel<<<(Bq * Hq * Lq) / ROWS, NTHR, SMEM_TOTAL>>>(x, out);
}